// round 16
// baseline (speedup 1.0000x reference)
#include <cuda_runtime.h>
#include <cuda.h>
#include <cstdint>

#define K_DIM      128
#define O_DIM      128
#define CHUNK      16          // rows per quad ring slot
#define THREADS    384         // 12 warps = 3 quads x 4 warps (one per SMSP)
#define QTHREADS   128
#define LDS_STRIDE 144         // row offset = 16 banks mod 32 -> conflict-free LDS.128
#define NBUF       6           // x-ring depth per quad (5 chunks in flight)
#define BUF_FLOATS (CHUNK * LDS_STRIDE)            // 2304
#define QUAD_FLOATS (NBUF * BUF_FLOATS)            // 13824
// C-buffers first (1024-aligned slabs for SW128): per quad 2 parities x 4 slabs x 2KB
#define CSLAB      2048                            // 16 rows x 128 B
#define CBUF_QUAD  (2 * 4 * CSLAB)                 // 16384
#define CBUF_TOTAL (3 * CBUF_QUAD)                 // 49152
#define RING_OFF_F (CBUF_TOTAL / 4)
#define SMEM_BYTES (CBUF_TOTAL + 3 * QUAD_FLOATS * 4)   // 215040

// x feeds the tf32 MMA as raw fp32 bits (HW truncates to tf32).
// Mean relative shrink of truncation = 2^-11 * ln2 = 3.38e-4; compensate on W.
#define W_SCALE 1.000338f

__device__ __forceinline__ uint32_t cvt_tf32(float f) {
    uint32_t r;
    asm("cvt.rna.tf32.f32 %0, %1;" : "=r"(r) : "f"(f));
    return r;
}
__device__ __forceinline__ void cp_async16(uint32_t smem_addr, const void* gptr) {
    asm volatile("cp.async.cg.shared.global [%0], [%1], 16;" :: "r"(smem_addr), "l"(gptr));
}
__device__ __forceinline__ void cp_commit() {
    asm volatile("cp.async.commit_group;");
}
__device__ __forceinline__ void quad_bar(int id) {
    asm volatile("bar.sync %0, %1;" :: "r"(id), "r"(QTHREADS) : "memory");
}
__device__ __forceinline__ void sts32(uint32_t addr, float v) {
    asm volatile("st.shared.b32 [%0], %1;" :: "r"(addr), "f"(v) : "memory");
}
__device__ __forceinline__ void tma_store_2d(const CUtensorMap* map, int cx, int cy,
                                             uint32_t saddr) {
    asm volatile("cp.async.bulk.tensor.2d.global.shared::cta.tile.bulk_group "
                 "[%0, {%1, %2}], [%3];"
                 :: "l"(map), "r"(cx), "r"(cy), "r"(saddr) : "memory");
}

// k-permutation (double-step): MMA step s, thread t covers logical k {t, t+4}
// <- physical cols {16(s>>1)+4t+2(s&1), +1}. One float4 at col 16sp+4t feeds
// steps 2sp (x,y) and 2sp+1 (z,w). Applied to A and B -> GEMM unchanged.
// n-permutation: n8-tile tt logical col n <- physical col 8tt + n/2 + 4(n&1)
// -> conflict-free C-slab STS.32.

__global__ void __launch_bounds__(THREADS, 1)
qlinear_tf32_tma3(const __grid_constant__ CUtensorMap omap,
                  const float* __restrict__ x,
                  const float* __restrict__ W,
                  int nrows, int nchunks)
{
    extern __shared__ __align__(1024) float smem[];
    const int tid  = threadIdx.x;
    const int lane = tid & 31;
    const int wid  = tid >> 5;
    const int qid  = wid >> 2;          // quad 0..2
    const int wo   = wid & 3;           // o-group within quad (col group = slab)
    const int tidq = tid & (QTHREADS - 1);
    const uint32_t smem_a = (uint32_t)__cvta_generic_to_shared(smem);

    float* qsm = smem + RING_OFF_F + qid * QUAD_FLOATS;
    const uint32_t qsm_a  = smem_a + (uint32_t)(RING_OFF_F + qid * QUAD_FLOATS) * 4;
    const uint32_t cbuf_a = smem_a + (uint32_t)(qid * CBUF_QUAD);
    const int barid = 1 + qid;

    const int c0 = blockIdx.x * 3 + qid;        // this quad's interleaved chunk stream
    const int st = gridDim.x * 3;

    auto stage = [&](int chunk, int buf) {
        if (chunk < nchunks) {
            const int row0 = chunk * CHUNK;
            const uint32_t base = qsm_a + (uint32_t)(buf * BUF_FLOATS) * 4;
            if (row0 + CHUNK <= nrows) {            // fast path: no per-row clamp
                #pragma unroll
                for (int j = 0; j < 4; j++) {
                    int flat = tidq + j * QTHREADS; // 0..511 float4s
                    int r  = flat >> 5;
                    int c4 = flat & 31;
                    cp_async16(base + (uint32_t)(r * LDS_STRIDE + c4 * 4) * 4,
                               x + (size_t)(row0 + r) * K_DIM + c4 * 4);
                }
            } else {
                #pragma unroll
                for (int j = 0; j < 4; j++) {
                    int flat = tidq + j * QTHREADS;
                    int r  = flat >> 5;
                    int c4 = flat & 31;
                    int gr = row0 + r;
                    if (gr >= nrows) gr = nrows - 1;
                    cp_async16(base + (uint32_t)(r * LDS_STRIDE + c4 * 4) * 4,
                               x + (size_t)gr * K_DIM + c4 * 4);
                }
            }
        }
    };

    stage(c0 + 0 * st, 0); cp_commit();
    stage(c0 + 1 * st, 1); cp_commit();
    stage(c0 + 2 * st, 2); cp_commit();
    stage(c0 + 3 * st, 3); cp_commit();
    stage(c0 + 4 * st, 4); cp_commit();

    const int q = lane >> 2;        // groupID (0..7)
    const int t = lane & 3;         // threadID in group (0..3)

    // ---- B fragments from gmem (L2-served, one-time), k- and n-permuted ----
    uint32_t Bf[16][4][2];
    #pragma unroll
    for (int s = 0; s < 16; s++) {
        const int col = 16 * (s >> 1) + 4 * t + 2 * (s & 1);
        #pragma unroll
        for (int tt = 0; tt < 4; tt++) {
            const int n = wo * 32 + 8 * tt + (q >> 1) + 4 * (q & 1);
            float2 w = *reinterpret_cast<const float2*>(W + n * K_DIM + col);
            Bf[s][tt][0] = cvt_tf32(w.x * W_SCALE);
            Bf[s][tt][1] = cvt_tf32(w.y * W_SCALE);
        }
    }

    // C-slab STS addressing: off = row*128 + tt*32 + j*16 + t*4, SW128 swizzle
    const uint32_t sw_mask = (uint32_t)(q << 4);
    const uint32_t cA = (uint32_t)(q * 128 + t * 4);
    const uint32_t thread_xoff = (uint32_t)(q * LDS_STRIDE + 4 * t);

    // ---- main pipeline: ring fully unrolled so buf/parity are compile-time ----
    int c = c0;
    while (c < nchunks) {
        #pragma unroll
        for (int u = 0; u < NBUF; u++) {
            if (c >= nchunks) break;

            asm volatile("cp.async.wait_group 4;");
            quad_bar(barid);                        // chunk staged for whole quad;
                                                    // also orders parity-slab reuse

            stage(c + 5 * st, (u + 5) % NBUF);      // compile-time slot
            cp_commit();

            const float* xb = qsm + u * BUF_FLOATS + thread_xoff;

            float acc[4][4];
            #pragma unroll
            for (int tt = 0; tt < 4; tt++)
                #pragma unroll
                for (int e = 0; e < 4; e++) acc[tt][e] = 0.0f;

            #pragma unroll
            for (int sp = 0; sp < 8; sp++) {        // step-pair: one LDS.128 per row
                float4 v0 = *reinterpret_cast<const float4*>(xb + sp * 16);
                float4 v1 = *reinterpret_cast<const float4*>(xb + 8 * LDS_STRIDE + sp * 16);
                #pragma unroll
                for (int h = 0; h < 2; h++) {
                    const int s = 2 * sp + h;
                    const uint32_t a0 = __float_as_uint(h ? v0.z : v0.x);
                    const uint32_t a2 = __float_as_uint(h ? v0.w : v0.y);
                    const uint32_t a1 = __float_as_uint(h ? v1.z : v1.x);
                    const uint32_t a3 = __float_as_uint(h ? v1.w : v1.y);
                    #pragma unroll
                    for (int tt = 0; tt < 4; tt++) {
                        asm volatile(
                            "mma.sync.aligned.m16n8k8.row.col.f32.tf32.tf32.f32 "
                            "{%0,%1,%2,%3}, {%4,%5,%6,%7}, {%8,%9}, {%0,%1,%2,%3};"
                            : "+f"(acc[tt][0]), "+f"(acc[tt][1]),
                              "+f"(acc[tt][2]), "+f"(acc[tt][3])
                            : "r"(a0), "r"(a1), "r"(a2), "r"(a3),
                              "r"(Bf[s][tt][0]), "r"(Bf[s][tt][1]));
                    }
                }
            }

            // ---- warp-local epilogue: STS -> fence -> syncwarp -> lane0 TMA ----
            const uint32_t slab = cbuf_a + (uint32_t)(((u & 1) * 4 + wo) * CSLAB);
            const uint32_t b0 = slab + cA;
            #pragma unroll
            for (int tt = 0; tt < 4; tt++) {
                const uint32_t clo = ((uint32_t)(tt * 32)      ^ sw_mask);
                const uint32_t chi = ((uint32_t)(tt * 32 + 16) ^ sw_mask);
                sts32(b0 + clo,        acc[tt][0]);
                sts32(b0 + chi,        acc[tt][1]);
                sts32(b0 + clo + 1024, acc[tt][2]);
                sts32(b0 + chi + 1024, acc[tt][3]);
            }
            asm volatile("fence.proxy.async.shared::cta;" ::: "memory");
            __syncwarp();
            if (lane == 0) {
                tma_store_2d(&omap, 32 * wo, c * CHUNK, slab);
                asm volatile("cp.async.bulk.commit_group;" ::: "memory");
                // keep <=1 unread group: this parity's slab from 2 chunks ago is free
                asm volatile("cp.async.bulk.wait_group.read 1;" ::: "memory");
            }

            c += st;
        }
    }

    // drain outstanding bulk stores before exit
    if (lane == 0)
        asm volatile("cp.async.bulk.wait_group 0;" ::: "memory");
}

extern "C" void kernel_launch(void* const* d_in, const int* in_sizes, int n_in,
                              void* d_out, int out_size)
{
    const float* x = (const float*)d_in[0];
    const float* W = (const float*)d_in[1];
    float* out = (float*)d_out;

    const int nrows   = in_sizes[0] / K_DIM;
    const int nchunks = (nrows + CHUNK - 1) / CHUNK;

    typedef CUresult (*EncFn)(CUtensorMap*, CUtensorMapDataType, cuuint32_t, void*,
                              const cuuint64_t*, const cuuint64_t*, const cuuint32_t*,
                              const cuuint32_t*, CUtensorMapInterleave, CUtensorMapSwizzle,
                              CUtensorMapL2promotion, CUtensorMapFloatOOBfill);
    void* fp = nullptr;
    cudaDriverEntryPointQueryResult qr;
    cudaGetDriverEntryPointByVersion("cuTensorMapEncodeTiled", &fp, 12000,
                                     cudaEnableDefault, &qr);
    EncFn enc = (EncFn)fp;

    CUtensorMap omap;
    cuuint64_t dims[2]    = {O_DIM, (cuuint64_t)nrows};
    cuuint64_t strides[1] = {O_DIM * sizeof(float)};
    cuuint32_t box[2]     = {32, CHUNK};           // 32 f32 = 128 B (SW128 atom)
    cuuint32_t es[2]      = {1, 1};
    enc(&omap, CU_TENSOR_MAP_DATA_TYPE_FLOAT32, 2, (void*)out, dims, strides, box, es,
        CU_TENSOR_MAP_INTERLEAVE_NONE, CU_TENSOR_MAP_SWIZZLE_128B,
        CU_TENSOR_MAP_L2_PROMOTION_L2_128B, CU_TENSOR_MAP_FLOAT_OOB_FILL_NONE);

    cudaFuncSetAttribute(qlinear_tf32_tma3,
                         cudaFuncAttributeMaxDynamicSharedMemorySize, SMEM_BYTES);

    int sms = 148;
    cudaDeviceGetAttribute(&sms, cudaDevAttrMultiProcessorCount, 0);
    int grid = sms;
    int need = (nchunks + 2) / 3;
    if (grid > need) grid = need;
    if (grid < 1) grid = 1;

    qlinear_tf32_tma3<<<grid, THREADS, SMEM_BYTES>>>(omap, x, W, nrows, nchunks);
}

// round 17
// speedup vs baseline: 1.0432x; 1.0432x over previous
#include <cuda_runtime.h>
#include <cuda.h>
#include <cstdint>

#define K_DIM      128
#define O_DIM      128
#define CHUNK      16          // rows per quad ring slot
#define THREADS    384         // 12 warps = 3 quads x 4 warps (one per SMSP)
#define QTHREADS   128
#define NBUF       6           // x-ring depth per quad (5 chunks in flight)
#define XSLAB      2048        // 16 rows x 128 B (SW128 slab, 32 f32 wide)
#define XSLOT      (4 * XSLAB)             // 8 KB = one 16x128 f32 chunk
#define XRING_QUAD (NBUF * XSLOT)          // 49152
#define CSLAB      2048
#define CBUF_QUAD  (2 * 4 * CSLAB)         // 16384
#define CBUF_TOTAL (3 * CBUF_QUAD)         // 49152
#define XRING_OFF  CBUF_TOTAL
#define MBAR_OFF   (XRING_OFF + 3 * XRING_QUAD)   // 196608
#define SMEM_BYTES (MBAR_OFF + 512)               // 197120

// x feeds the tf32 MMA as raw fp32 bits (HW truncates to tf32).
// Mean relative shrink of truncation = 2^-11 * ln2 = 3.38e-4; compensate on W.
#define W_SCALE 1.000338f

__device__ __forceinline__ uint32_t cvt_tf32(float f) {
    uint32_t r;
    asm("cvt.rna.tf32.f32 %0, %1;" : "=r"(r) : "f"(f));
    return r;
}
__device__ __forceinline__ void mbar_init(uint32_t a, uint32_t cnt) {
    asm volatile("mbarrier.init.shared.b64 [%0], %1;" :: "r"(a), "r"(cnt) : "memory");
}
__device__ __forceinline__ void mbar_arrive(uint32_t a) {
    asm volatile("mbarrier.arrive.shared.b64 _, [%0];" :: "r"(a) : "memory");
}
__device__ __forceinline__ void mbar_expect_tx(uint32_t a, uint32_t bytes) {
    asm volatile("mbarrier.arrive.expect_tx.shared.b64 _, [%0], %1;"
                 :: "r"(a), "r"(bytes) : "memory");
}
__device__ __forceinline__ void mbar_wait(uint32_t a, uint32_t parity) {
    uint32_t done;
    asm volatile("{\n\t.reg .pred p;\n\t"
                 "mbarrier.try_wait.parity.acquire.cta.shared::cta.b64 p, [%1], %2;\n\t"
                 "selp.b32 %0, 1, 0, p;\n\t}"
                 : "=r"(done) : "r"(a), "r"(parity) : "memory");
    if (!done) {
        asm volatile("{\n\t.reg .pred P1;\n\t"
                     "W_%=:\n\t"
                     "mbarrier.try_wait.parity.acquire.cta.shared::cta.b64 P1, [%0], %1, 0x989680;\n\t"
                     "@P1 bra.uni D_%=;\n\t"
                     "bra.uni W_%=;\n\t"
                     "D_%=:\n\t}"
                     :: "r"(a), "r"(parity) : "memory");
    }
}
__device__ __forceinline__ void sts32(uint32_t addr, float v) {
    asm volatile("st.shared.b32 [%0], %1;" :: "r"(addr), "f"(v) : "memory");
}
__device__ __forceinline__ float2 lds64(uint32_t addr) {
    float2 v;
    asm volatile("ld.shared.v2.f32 {%0, %1}, [%2];"
                 : "=f"(v.x), "=f"(v.y) : "r"(addr));
    return v;
}
__device__ __forceinline__ void tma_load_2d(uint32_t saddr, const CUtensorMap* map,
                                            int cx, int cy, uint32_t mbar) {
    asm volatile("cp.async.bulk.tensor.2d.shared::cta.global.tile.mbarrier::complete_tx::bytes "
                 "[%0], [%1, {%2, %3}], [%4];"
                 :: "r"(saddr), "l"(map), "r"(cx), "r"(cy), "r"(mbar) : "memory");
}
__device__ __forceinline__ void tma_store_2d(const CUtensorMap* map, int cx, int cy,
                                             uint32_t saddr) {
    asm volatile("cp.async.bulk.tensor.2d.global.shared::cta.tile.bulk_group "
                 "[%0, {%1, %2}], [%3];"
                 :: "l"(map), "r"(cx), "r"(cy), "r"(saddr) : "memory");
}

// k-permutation (SW128-compatible): step s, thread t covers logical k {t, t+4}
// <- physical cols {32(s>>2)+4(s&3)+2(t&1)+16(t>>1), +1}. Applied to A and B
// -> GEMM unchanged. In the swizzled slab the A LDS.64 byte address becomes
//   q*128 ^ 8(t&1) ^ 64(t>>1) ^ (q<<4) ^ 16(s&3)
// (all fields disjoint): conflict-free phases, zero per-step address ALU.
// n-permutation: n8-tile tt logical col n <- physical col 8tt + n/2 + 4(n&1)
// -> conflict-free C-slab STS.32.

__global__ void __launch_bounds__(THREADS, 1)
qlinear_tf32_tma4(const __grid_constant__ CUtensorMap xmap,
                  const __grid_constant__ CUtensorMap omap,
                  const float* __restrict__ W,
                  int nrows, int nchunks)
{
    extern __shared__ __align__(1024) float smem[];
    const int tid  = threadIdx.x;
    const int lane = tid & 31;
    const int wid  = tid >> 5;
    const int qid  = wid >> 2;          // quad 0..2
    const int wo   = wid & 3;           // o-group within quad (col group = slab)
    const int tidq = tid & (QTHREADS - 1);
    const uint32_t smem_a  = (uint32_t)__cvta_generic_to_shared(smem);
    const uint32_t xring_a = smem_a + (uint32_t)(XRING_OFF + qid * XRING_QUAD);
    const uint32_t cbuf_a  = smem_a + (uint32_t)(qid * CBUF_QUAD);
    const uint32_t mb      = smem_a + (uint32_t)(MBAR_OFF + qid * 96);
    // full[i] @ mb+8i, empty[i] @ mb+48+8i

    if (tid == 0) {
        for (int k = 0; k < 3; k++)
            #pragma unroll
            for (int i = 0; i < NBUF; i++) {
                mbar_init(smem_a + MBAR_OFF + k * 96 + i * 8, 1);       // full
                mbar_init(smem_a + MBAR_OFF + k * 96 + 48 + i * 8, 4);  // empty
            }
    }
    __syncthreads();

    const int c0 = blockIdx.x * 3 + qid;        // this quad's interleaved chunk stream
    const int st = gridDim.x * 3;

    // prologue: stage slots 0..4 via TMA (one elected thread per quad)
    if (tidq == 0) {
        #pragma unroll
        for (int i = 0; i < NBUF - 1; i++) {
            int cc = c0 + i * st;
            if (cc < nchunks) {
                mbar_expect_tx(mb + i * 8, XSLOT);
                uint32_t dst = xring_a + (uint32_t)(i * XSLOT);
                #pragma unroll
                for (int g = 0; g < 4; g++)
                    tma_load_2d(dst + g * XSLAB, &xmap, 32 * g, cc * CHUNK, mb + i * 8);
            }
        }
    }

    const int q = lane >> 2;        // groupID (0..7)
    const int t = lane & 3;         // threadID in group (0..3)

    // ---- B fragments from gmem (L2-served, one-time), k- and n-permuted ----
    uint32_t Bf[16][4][2];
    #pragma unroll
    for (int s = 0; s < 16; s++) {
        const int col = 32 * (s >> 2) + 4 * (s & 3) + 2 * (t & 1) + 16 * (t >> 1);
        #pragma unroll
        for (int tt = 0; tt < 4; tt++) {
            const int n = wo * 32 + 8 * tt + (q >> 1) + 4 * (q & 1);
            float2 w = *reinterpret_cast<const float2*>(W + n * K_DIM + col);
            Bf[s][tt][0] = cvt_tf32(w.x * W_SCALE);
            Bf[s][tt][1] = cvt_tf32(w.y * W_SCALE);
        }
    }

    // C-slab STS addressing (unchanged)
    const uint32_t sw_mask = (uint32_t)(q << 4);
    const uint32_t cA = (uint32_t)(q * 128 + t * 4);
    // A-read thread constant (byte offset within slot, pre-swizzled)
    const uint32_t Cx = (uint32_t)(q * 128) ^ (uint32_t)(8 * (t & 1))
                      ^ (uint32_t)(64 * (t >> 1)) ^ (uint32_t)(q << 4);

    int fph = 0;                    // full-phase parity for current ring pass
    int c = c0;
    while (c < nchunks) {
        #pragma unroll
        for (int u = 0; u < NBUF; u++) {
            if (c >= nchunks) break;

            mbar_wait(mb + u * 8, (uint32_t)fph);           // x[c] arrived (acquire)

            // producer: stage chunk c+5 into the slot consumed last iteration
            const int cn = c + 5 * st;
            if (tidq == 0 && cn < nchunks) {
                const int ps = (u + 5) % NBUF;
                mbar_wait(mb + 48 + ps * 8,
                          (uint32_t)((u == 0) ? (fph ^ 1) : fph)); // slot free
                mbar_expect_tx(mb + ps * 8, XSLOT);
                uint32_t dst = xring_a + (uint32_t)(ps * XSLOT);
                #pragma unroll
                for (int g = 0; g < 4; g++)
                    tma_load_2d(dst + g * XSLAB, &xmap, 32 * g, cn * CHUNK,
                                mb + ps * 8);
            }

            const uint32_t abase = xring_a + (uint32_t)(u * XSLOT) + Cx;

            float acc[4][4];
            #pragma unroll
            for (int tt = 0; tt < 4; tt++)
                #pragma unroll
                for (int e = 0; e < 4; e++) acc[tt][e] = 0.0f;

            #pragma unroll
            for (int s = 0; s < 16; s++) {
                // slab (s>>2)*2048 as immediate; XOR only touches bits 4-5
                const uint32_t addr = (abase ^ (uint32_t)(16 * (s & 3)))
                                    + (uint32_t)((s >> 2) * XSLAB);
                float2 f0 = lds64(addr);            // row q
                float2 f1 = lds64(addr + 1024);     // row q+8 (same swizzle bits)
                const uint32_t a0 = __float_as_uint(f0.x);
                const uint32_t a2 = __float_as_uint(f0.y);
                const uint32_t a1 = __float_as_uint(f1.x);
                const uint32_t a3 = __float_as_uint(f1.y);
                #pragma unroll
                for (int tt = 0; tt < 4; tt++) {
                    asm volatile(
                        "mma.sync.aligned.m16n8k8.row.col.f32.tf32.tf32.f32 "
                        "{%0,%1,%2,%3}, {%4,%5,%6,%7}, {%8,%9}, {%0,%1,%2,%3};"
                        : "+f"(acc[tt][0]), "+f"(acc[tt][1]),
                          "+f"(acc[tt][2]), "+f"(acc[tt][3])
                        : "r"(a0), "r"(a1), "r"(a2), "r"(a3),
                          "r"(Bf[s][tt][0]), "r"(Bf[s][tt][1]));
                }
            }

            // all this warp's reads of slot u are complete -> release it
            if (lane == 0) mbar_arrive(mb + 48 + u * 8);

            // ---- warp-local epilogue: STS -> fence -> syncwarp -> lane0 TMA ----
            const uint32_t slab = cbuf_a + (uint32_t)(((u & 1) * 4 + wo) * CSLAB);
            const uint32_t b0 = slab + cA;
            #pragma unroll
            for (int tt = 0; tt < 4; tt++) {
                const uint32_t clo = ((uint32_t)(tt * 32)      ^ sw_mask);
                const uint32_t chi = ((uint32_t)(tt * 32 + 16) ^ sw_mask);
                sts32(b0 + clo,        acc[tt][0]);
                sts32(b0 + chi,        acc[tt][1]);
                sts32(b0 + clo + 1024, acc[tt][2]);
                sts32(b0 + chi + 1024, acc[tt][3]);
            }
            asm volatile("fence.proxy.async.shared::cta;" ::: "memory");
            __syncwarp();
            if (lane == 0) {
                tma_store_2d(&omap, 32 * wo, c * CHUNK, slab);
                asm volatile("cp.async.bulk.commit_group;" ::: "memory");
                asm volatile("cp.async.bulk.wait_group.read 1;" ::: "memory");
            }

            c += st;
        }
        fph ^= 1;
    }

    if (lane == 0)
        asm volatile("cp.async.bulk.wait_group 0;" ::: "memory");
}

extern "C" void kernel_launch(void* const* d_in, const int* in_sizes, int n_in,
                              void* d_out, int out_size)
{
    const float* x = (const float*)d_in[0];
    const float* W = (const float*)d_in[1];
    float* out = (float*)d_out;

    const int nrows   = in_sizes[0] / K_DIM;
    const int nchunks = (nrows + CHUNK - 1) / CHUNK;

    typedef CUresult (*EncFn)(CUtensorMap*, CUtensorMapDataType, cuuint32_t, void*,
                              const cuuint64_t*, const cuuint64_t*, const cuuint32_t*,
                              const cuuint32_t*, CUtensorMapInterleave, CUtensorMapSwizzle,
                              CUtensorMapL2promotion, CUtensorMapFloatOOBfill);
    void* fp = nullptr;
    cudaDriverEntryPointQueryResult qr;
    cudaGetDriverEntryPointByVersion("cuTensorMapEncodeTiled", &fp, 12000,
                                     cudaEnableDefault, &qr);
    EncFn enc = (EncFn)fp;

    cuuint32_t box[2] = {32, CHUNK};               // 32 f32 = 128 B (SW128 atom)
    cuuint32_t es[2]  = {1, 1};

    CUtensorMap xmap;
    {
        cuuint64_t dims[2]    = {K_DIM, (cuuint64_t)nrows};
        cuuint64_t strides[1] = {K_DIM * sizeof(float)};
        enc(&xmap, CU_TENSOR_MAP_DATA_TYPE_FLOAT32, 2, (void*)x, dims, strides,
            box, es, CU_TENSOR_MAP_INTERLEAVE_NONE, CU_TENSOR_MAP_SWIZZLE_128B,
            CU_TENSOR_MAP_L2_PROMOTION_L2_128B, CU_TENSOR_MAP_FLOAT_OOB_FILL_NONE);
    }
    CUtensorMap omap;
    {
        cuuint64_t dims[2]    = {O_DIM, (cuuint64_t)nrows};
        cuuint64_t strides[1] = {O_DIM * sizeof(float)};
        enc(&omap, CU_TENSOR_MAP_DATA_TYPE_FLOAT32, 2, (void*)out, dims, strides,
            box, es, CU_TENSOR_MAP_INTERLEAVE_NONE, CU_TENSOR_MAP_SWIZZLE_128B,
            CU_TENSOR_MAP_L2_PROMOTION_L2_128B, CU_TENSOR_MAP_FLOAT_OOB_FILL_NONE);
    }

    cudaFuncSetAttribute(qlinear_tf32_tma4,
                         cudaFuncAttributeMaxDynamicSharedMemorySize, SMEM_BYTES);

    int sms = 148;
    cudaDeviceGetAttribute(&sms, cudaDevAttrMultiProcessorCount, 0);
    int grid = sms;
    int need = (nchunks + 2) / 3;
    if (grid > need) grid = need;
    if (grid < 1) grid = 1;

    qlinear_tf32_tma4<<<grid, THREADS, SMEM_BYTES>>>(xmap, omap, W, nrows, nchunks);
}